// round 1
// baseline (speedup 1.0000x reference)
#include <cuda_runtime.h>
#include <math.h>
#include <stdint.h>

// ---------------------------------------------------------------------------
// HE_ColorNormalization: 100-iter rank-4 NMF (beta=2 multiplicative updates)
// on optical density V = -log(clip(pic,0.01,0.99)), then 0.99-quantile
// normalization of concentrations and recomposition with target stains.
//
// Inputs (metadata order):
//   d_in[0] pic      float32 (3,1024,1024)
//   d_in[1] W_target float32 (3,4)
//   d_in[2] Ht_RM    float32 ()       scalar
//   d_in[3] W0       float32 (N,4)
//   d_in[4] H0       float32 (3,4)
// Output: float32 (3,1024,1024)
// ---------------------------------------------------------------------------

#define N_PIX   1048576
#define N_ITERS 100
#define EPSF    1e-8f
#define NCTA    148
#define NTHR    512
#define TOTAL   (4 * N_PIX)          // 4194304 concentration values
#define RANK0   4152359u             // floor(0.99*(TOTAL-1))
#define RANK1   4152360u
#define HREP    8                    // hist1 replication factor

// Scratch (static device globals: no allocation allowed)
__device__ float    g_V[3 * N_PIX];          // optical density, 3 planes
__device__ float4   g_Wc[N_PIX];             // concentrations (N,4)
__device__ float    g_Hd[12];                // stain matrix (3,4)
__device__ float    g_part[22 * NCTA];       // per-CTA partials, value-major
__device__ unsigned g_hist1[HREP * 65536];   // replicated top-16-bit histogram
__device__ unsigned g_hist2a[65536];
__device__ unsigned g_hist2b[65536];
__device__ unsigned g_bA, g_bB, g_cumA, g_cumB;
__device__ float    g_scale;

// ---------------------------------------------------------------------------
// init: V from pic, Wc = W0, Hd = H0, zero histograms
// ---------------------------------------------------------------------------
__global__ void k_init(const float* __restrict__ pic,
                       const float* __restrict__ W0,
                       const float* __restrict__ H0) {
    int i = blockIdx.x * blockDim.x + threadIdx.x;
    int stride = gridDim.x * blockDim.x;
    const float4* w0 = (const float4*)W0;
    for (int p = i; p < N_PIX; p += stride) {
#pragma unroll
        for (int c = 0; c < 3; c++) {
            float v = pic[c * N_PIX + p];
            v = fminf(fmaxf(v, 0.01f), 0.99f);
            g_V[c * N_PIX + p] = -logf(v);
        }
        g_Wc[p] = w0[p];
    }
    for (int h = i; h < HREP * 65536; h += stride) g_hist1[h] = 0u;
    for (int h = i; h < 65536; h += stride) { g_hist2a[h] = 0u; g_hist2b[h] = 0u; }
    if (i < 12) g_Hd[i] = H0[i];
}

// ---------------------------------------------------------------------------
// One NMF iteration, part 1: update all Wc rows, accumulate A (12) + Bsym (10)
// partials per CTA (no float atomics -> deterministic).
// ---------------------------------------------------------------------------
__global__ __launch_bounds__(NTHR) void k_rows() {
    __shared__ float sHd[12];
    if (threadIdx.x < 12) sHd[threadIdx.x] = g_Hd[threadIdx.x];
    __syncthreads();

    float hd[12];
#pragma unroll
    for (int t = 0; t < 12; t++) hd[t] = sHd[t];

    // Gram G[k][j] = sum_c Hd[c][k]*Hd[c][j]
    float G[16];
#pragma unroll
    for (int k = 0; k < 4; k++)
#pragma unroll
        for (int j = 0; j < 4; j++)
            G[k * 4 + j] = hd[k] * hd[j] + hd[4 + k] * hd[4 + j] + hd[8 + k] * hd[8 + j];

    float acc[22];
#pragma unroll
    for (int t = 0; t < 22; t++) acc[t] = 0.0f;

    int tid = blockIdx.x * blockDim.x + threadIdx.x;
    const int stride = NCTA * NTHR;
    for (int p = tid; p < N_PIX; p += stride) {
        float v0 = g_V[p];
        float v1 = g_V[N_PIX + p];
        float v2 = g_V[2 * N_PIX + p];
        float4 w4 = g_Wc[p];
        float w[4] = {w4.x, w4.y, w4.z, w4.w};
        float nw[4];
#pragma unroll
        for (int j = 0; j < 4; j++) {
            float num = v0 * hd[j] + v1 * hd[4 + j] + v2 * hd[8 + j];
            float den = w[0] * G[j] + w[1] * G[4 + j] + w[2] * G[8 + j] + w[3] * G[12 + j] + EPSF;
            nw[j] = w[j] * __fdividef(num, den);
        }
        g_Wc[p] = make_float4(nw[0], nw[1], nw[2], nw[3]);
#pragma unroll
        for (int j = 0; j < 4; j++) {
            acc[j]     += v0 * nw[j];
            acc[4 + j] += v1 * nw[j];
            acc[8 + j] += v2 * nw[j];
        }
        int t = 12;
#pragma unroll
        for (int j = 0; j < 4; j++)
#pragma unroll
            for (int k = j; k < 4; k++) { acc[t] += nw[j] * nw[k]; t++; }
    }

    // warp tree reduce all 22
#pragma unroll
    for (int t = 0; t < 22; t++)
#pragma unroll
        for (int off = 16; off > 0; off >>= 1)
            acc[t] += __shfl_down_sync(0xFFFFFFFFu, acc[t], off);

    __shared__ float red[NTHR / 32][22];
    int warp = threadIdx.x >> 5, lane = threadIdx.x & 31;
    if (lane == 0) {
#pragma unroll
        for (int t = 0; t < 22; t++) red[warp][t] = acc[t];
    }
    __syncthreads();
    if (threadIdx.x < 22) {
        float s = 0.0f;
#pragma unroll
        for (int w = 0; w < NTHR / 32; w++) s += red[w][threadIdx.x];
        g_part[threadIdx.x * NCTA + blockIdx.x] = s;
    }
}

// ---------------------------------------------------------------------------
// One NMF iteration, part 2: reduce 148 partials, update Hd (3,4).
// ---------------------------------------------------------------------------
__global__ void k_hd() {
    __shared__ float tot[22];
    int warp = threadIdx.x >> 5, lane = threadIdx.x & 31;
    if (warp < 22) {
        float s = 0.0f;
        for (int b = lane; b < NCTA; b += 32) s += g_part[warp * NCTA + b];
#pragma unroll
        for (int off = 16; off > 0; off >>= 1) s += __shfl_down_sync(0xFFFFFFFFu, s, off);
        if (lane == 0) tot[warp] = s;
    }
    __syncthreads();
    if (threadIdx.x == 0) {
        float hd[12];
#pragma unroll
        for (int t = 0; t < 12; t++) hd[t] = g_Hd[t];
        // symmetric B -> full 4x4
        const int map[16] = {0,1,2,3, 1,4,5,6, 2,5,7,8, 3,6,8,9};
        float B[16];
#pragma unroll
        for (int t = 0; t < 16; t++) B[t] = tot[12 + map[t]];
        float nhd[12];
#pragma unroll
        for (int c = 0; c < 3; c++)
#pragma unroll
            for (int j = 0; j < 4; j++) {
                float den = hd[c*4+0]*B[0*4+j] + hd[c*4+1]*B[1*4+j]
                          + hd[c*4+2]*B[2*4+j] + hd[c*4+3]*B[3*4+j] + EPSF;
                nhd[c*4+j] = hd[c*4+j] * tot[c*4+j] / den;
            }
#pragma unroll
        for (int t = 0; t < 12; t++) g_Hd[t] = nhd[t];
    }
}

// ---------------------------------------------------------------------------
// Quantile pass 1: replicated histogram over top 16 bits of float bit pattern
// (all concentrations are > 0, so uint32 order == float order).
// ---------------------------------------------------------------------------
__global__ void k_hist1() {
    const float* p = (const float*)g_Wc;
    unsigned* hist = &g_hist1[(blockIdx.x & (HREP - 1)) * 65536];
    int i = blockIdx.x * blockDim.x + threadIdx.x;
    int stride = gridDim.x * blockDim.x;
    for (; i < TOTAL; i += stride) {
        unsigned bits = __float_as_uint(p[i]);
        atomicAdd(&hist[bits >> 16], 1u);
    }
}

// ---------------------------------------------------------------------------
// Select buckets containing order statistics RANK0 and RANK1.
// ---------------------------------------------------------------------------
__global__ void k_sel1() {
    __shared__ unsigned chunk[1024];
    int tid = threadIdx.x;
    unsigned s = 0;
    for (int k = 0; k < 64; k++) {
        unsigned bin = tid * 64 + k;
        unsigned c = 0;
#pragma unroll
        for (int r = 0; r < HREP; r++) c += g_hist1[r * 65536 + bin];
        s += c;
    }
    chunk[tid] = s;
    __syncthreads();
    if (tid == 0) {
        unsigned run = 0;
        for (int i = 0; i < 1024; i++) { unsigned c = chunk[i]; chunk[i] = run; run += c; }
    }
    __syncthreads();
    unsigned c = chunk[tid];
    for (int k = 0; k < 64; k++) {
        unsigned bin = tid * 64 + k;
        unsigned h = 0;
#pragma unroll
        for (int r = 0; r < HREP; r++) h += g_hist1[r * 65536 + bin];
        if (RANK0 >= c && RANK0 < c + h) { g_bA = bin; g_cumA = c; }
        if (RANK1 >= c && RANK1 < c + h) { g_bB = bin; g_cumB = c; }
        c += h;
    }
}

// ---------------------------------------------------------------------------
// Quantile pass 2: low-16-bit histograms restricted to the selected buckets.
// ---------------------------------------------------------------------------
__global__ void k_hist2() {
    unsigned bA = g_bA, bB = g_bB;
    const float* p = (const float*)g_Wc;
    int i = blockIdx.x * blockDim.x + threadIdx.x;
    int stride = gridDim.x * blockDim.x;
    for (; i < TOTAL; i += stride) {
        unsigned bits = __float_as_uint(p[i]);
        unsigned hi = bits >> 16;
        if (hi == bA) atomicAdd(&g_hist2a[bits & 0xFFFFu], 1u);
        if (hi == bB) atomicAdd(&g_hist2b[bits & 0xFFFFu], 1u);
    }
}

__device__ __forceinline__ void select_low(const unsigned* __restrict__ hist,
                                           unsigned rank, unsigned hi_bits,
                                           unsigned* chunk, float* out_val) {
    int tid = threadIdx.x;
    unsigned s = 0;
    for (int k = 0; k < 64; k++) s += hist[tid * 64 + k];
    chunk[tid] = s;
    __syncthreads();
    if (tid == 0) {
        unsigned run = 0;
        for (int i = 0; i < 1024; i++) { unsigned c = chunk[i]; chunk[i] = run; run += c; }
    }
    __syncthreads();
    unsigned c = chunk[tid];
    for (int k = 0; k < 64; k++) {
        unsigned h = hist[tid * 64 + k];
        if (rank >= c && rank < c + h)
            *out_val = __uint_as_float((hi_bits << 16) | (unsigned)(tid * 64 + k));
        c += h;
    }
    __syncthreads();
}

__global__ void k_sel2(const float* __restrict__ HtRM) {
    __shared__ unsigned chunk[1024];
    __shared__ float vsh[2];
    select_low(g_hist2a, RANK0 - g_cumA, g_bA, chunk, &vsh[0]);
    select_low(g_hist2b, RANK1 - g_cumB, g_bB, chunk, &vsh[1]);
    if (threadIdx.x == 0) {
        double pos = 0.99 * (double)(TOTAL - 1);
        double fr  = pos - floor(pos);   // 0.97
        double q = (double)vsh[0] + fr * ((double)vsh[1] - (double)vsh[0]);
        g_scale = HtRM[0] / (float)q;
    }
}

// ---------------------------------------------------------------------------
// Recompose: out = clip(exp(-(W_target @ (Wc^T * scale))), 0, 1)
// ---------------------------------------------------------------------------
__global__ void k_final(const float* __restrict__ Wt, float* __restrict__ out) {
    __shared__ float sw[12];
    if (threadIdx.x < 12) sw[threadIdx.x] = Wt[threadIdx.x];
    __syncthreads();
    float wt[12];
#pragma unroll
    for (int t = 0; t < 12; t++) wt[t] = sw[t];
    float sc = g_scale;
    int i = blockIdx.x * blockDim.x + threadIdx.x;
    int stride = gridDim.x * blockDim.x;
    for (int p = i; p < N_PIX; p += stride) {
        float4 c4 = g_Wc[p];
        float h0 = c4.x * sc, h1 = c4.y * sc, h2 = c4.z * sc, h3 = c4.w * sc;
#pragma unroll
        for (int c = 0; c < 3; c++) {
            float t = wt[c*4+0]*h0 + wt[c*4+1]*h1 + wt[c*4+2]*h2 + wt[c*4+3]*h3;
            float o = __expf(-t);
            out[c * N_PIX + p] = fminf(fmaxf(o, 0.0f), 1.0f);
        }
    }
}

// ---------------------------------------------------------------------------
extern "C" void kernel_launch(void* const* d_in, const int* in_sizes, int n_in,
                              void* d_out, int out_size) {
    const float* pic = (const float*)d_in[0];
    const float* Wt  = (const float*)d_in[1];
    const float* Ht  = (const float*)d_in[2];
    const float* W0  = (const float*)d_in[3];
    const float* H0  = (const float*)d_in[4];
    float* out = (float*)d_out;

    k_init<<<592, 256>>>(pic, W0, H0);
    for (int it = 0; it < N_ITERS; it++) {
        k_rows<<<NCTA, NTHR>>>();
        k_hd<<<1, 704>>>();
    }
    k_hist1<<<592, 256>>>();
    k_sel1<<<1, 1024>>>();
    k_hist2<<<592, 256>>>();
    k_sel2<<<1, 1024>>>(Ht);
    k_final<<<592, 256>>>(Wt, out);
}

// round 6
// speedup vs baseline: 1.2798x; 1.2798x over previous
#include <cuda_runtime.h>
#include <math.h>
#include <stdint.h>

// ---------------------------------------------------------------------------
// HE_ColorNormalization, persistent-kernel version.
//   d_in[0] pic float32 (3,1024,1024) | d_in[1] W_target (3,4) | d_in[2] Ht_RM ()
//   d_in[3] W0 (N,4) | d_in[4] H0 (3,4)    Output: float32 (3,1024,1024)
// ---------------------------------------------------------------------------

#define N_PIX   1048576
#define N_ITERS 100
#define EPSF    1e-8f
#define NTHR    512
#define GRID_MAX 1024
#define TOTAL   (4 * N_PIX)
#define RANK0   4152359u             // floor(0.99*(TOTAL-1))
#define RANK1   4152360u
#define HREP    16

// Scratch (static device globals: no allocation allowed)
__device__ float    g_V[3 * N_PIX];
__device__ float4   g_Wc[N_PIX];
__device__ float    g_part[2][22][GRID_MAX];  // double-buffered per-CTA partials
__device__ unsigned g_arrive;                 // barrier generation counter
__device__ unsigned g_hist1[HREP * 65536];
__device__ unsigned g_hist2a[65536];
__device__ unsigned g_hist2b[65536];
__device__ unsigned g_bA, g_bB, g_cumA, g_cumB;
__device__ float    g_scale;

// ---------------------------------------------------------------------------
__global__ void k_init(const float* __restrict__ pic,
                       const float* __restrict__ W0) {
    int i = blockIdx.x * blockDim.x + threadIdx.x;
    int stride = gridDim.x * blockDim.x;
    const float4* w0 = (const float4*)W0;
    for (int p = i; p < N_PIX; p += stride) {
#pragma unroll
        for (int c = 0; c < 3; c++) {
            float v = pic[c * N_PIX + p];
            v = fminf(fmaxf(v, 0.01f), 0.99f);
            g_V[c * N_PIX + p] = -logf(v);
        }
        g_Wc[p] = w0[p];
    }
    for (int h = i; h < HREP * 65536; h += stride) g_hist1[h] = 0u;
    for (int h = i; h < 65536; h += stride) { g_hist2a[h] = 0u; g_hist2b[h] = 0u; }
    if (i == 0) g_arrive = 0u;
}

// ---------------------------------------------------------------------------
// Persistent loop: 100 NMF iterations, one grid barrier per iteration.
// Every CTA redundantly reduces partials (fixed order -> deterministic) and
// recomputes Hd, so no second barrier / no 1-block kernel is needed.
// ---------------------------------------------------------------------------
__global__ __launch_bounds__(NTHR, 2) void k_loop(const float* __restrict__ H0) {
    __shared__ float sHd[12];
    __shared__ float red[NTHR / 32][22];
    __shared__ float tot[22];

    const int tid  = threadIdx.x;
    const int cta  = blockIdx.x;
    const int grid = gridDim.x;
    const int warp = tid >> 5, lane = tid & 31;

    if (tid < 12) sHd[tid] = H0[tid];
    __syncthreads();

    for (int iter = 0; iter < N_ITERS; iter++) {
        float hd[12];
#pragma unroll
        for (int t = 0; t < 12; t++) hd[t] = sHd[t];

        float G[16];
#pragma unroll
        for (int k = 0; k < 4; k++)
#pragma unroll
            for (int j = 0; j < 4; j++)
                G[k * 4 + j] = hd[k] * hd[j] + hd[4 + k] * hd[4 + j] + hd[8 + k] * hd[8 + j];

        float acc[22];
#pragma unroll
        for (int t = 0; t < 22; t++) acc[t] = 0.0f;

        const bool last = (iter == N_ITERS - 1);
        unsigned* hist = &g_hist1[(cta & (HREP - 1)) * 65536];

        for (int p = cta * NTHR + tid; p < N_PIX; p += grid * NTHR) {
            float v0 = g_V[p];
            float v1 = g_V[N_PIX + p];
            float v2 = g_V[2 * N_PIX + p];
            float4 w4 = g_Wc[p];
            float w[4] = {w4.x, w4.y, w4.z, w4.w};
            float nw[4];
#pragma unroll
            for (int j = 0; j < 4; j++) {
                float num = v0 * hd[j] + v1 * hd[4 + j] + v2 * hd[8 + j];
                float den = w[0] * G[j] + w[1] * G[4 + j] + w[2] * G[8 + j]
                          + w[3] * G[12 + j] + EPSF;
                nw[j] = w[j] * __fdividef(num, den);
            }
            g_Wc[p] = make_float4(nw[0], nw[1], nw[2], nw[3]);
#pragma unroll
            for (int j = 0; j < 4; j++) {
                acc[j]     += v0 * nw[j];
                acc[4 + j] += v1 * nw[j];
                acc[8 + j] += v2 * nw[j];
            }
            int t = 12;
#pragma unroll
            for (int j = 0; j < 4; j++)
#pragma unroll
                for (int k = j; k < 4; k++) { acc[t] += nw[j] * nw[k]; t++; }
            if (last) {
#pragma unroll
                for (int j = 0; j < 4; j++)
                    atomicAdd(&hist[__float_as_uint(nw[j]) >> 16], 1u);
            }
        }

        if (last) break;   // hist writes flushed by kernel completion

        // CTA-level reduction of the 22 accumulators
#pragma unroll
        for (int t = 0; t < 22; t++)
#pragma unroll
            for (int off = 16; off > 0; off >>= 1)
                acc[t] += __shfl_down_sync(0xFFFFFFFFu, acc[t], off);
        if (lane == 0) {
#pragma unroll
            for (int t = 0; t < 22; t++) red[warp][t] = acc[t];
        }
        __syncthreads();
        if (tid < 22) {
            float s = 0.0f;
#pragma unroll
            for (int w = 0; w < NTHR / 32; w++) s += red[w][tid];
            g_part[iter & 1][tid][cta] = s;
        }
        __syncthreads();

        // grid barrier (generation counter; reset each replay by k_init)
        if (tid == 0) {
            __threadfence();
            atomicAdd(&g_arrive, 1u);
            const unsigned target = (unsigned)(iter + 1) * (unsigned)grid;
            const volatile unsigned* va = &g_arrive;
            while (*va < target) __nanosleep(32);
            __threadfence();
        }
        __syncthreads();

        // every CTA reduces all partials in fixed order (deterministic)
        for (int v = warp; v < 22; v += NTHR / 32) {
            float s = 0.0f;
            for (int b = lane; b < grid; b += 32) s += g_part[iter & 1][v][b];
#pragma unroll
            for (int off = 16; off > 0; off >>= 1)
                s += __shfl_down_sync(0xFFFFFFFFu, s, off);
            if (lane == 0) tot[v] = s;
        }
        __syncthreads();

        if (tid == 0) {
            const int map[16] = {0,1,2,3, 1,4,5,6, 2,5,7,8, 3,6,8,9};
            float B[16];
#pragma unroll
            for (int t = 0; t < 16; t++) B[t] = tot[12 + map[t]];
#pragma unroll
            for (int c = 0; c < 3; c++)
#pragma unroll
                for (int j = 0; j < 4; j++) {
                    float den = hd[c*4+0]*B[0*4+j] + hd[c*4+1]*B[1*4+j]
                              + hd[c*4+2]*B[2*4+j] + hd[c*4+3]*B[3*4+j] + EPSF;
                    sHd[c*4+j] = hd[c*4+j] * tot[c*4+j] / den;
                }
        }
        __syncthreads();
    }
}

// ---------------------------------------------------------------------------
__global__ void k_sel1() {
    __shared__ unsigned chunk[1024];
    int tid = threadIdx.x;
    unsigned s = 0;
    for (int k = 0; k < 64; k++) {
        unsigned bin = tid * 64 + k;
        unsigned c = 0;
#pragma unroll
        for (int r = 0; r < HREP; r++) c += g_hist1[r * 65536 + bin];
        s += c;
    }
    chunk[tid] = s;
    __syncthreads();
    if (tid == 0) {
        unsigned run = 0;
        for (int i = 0; i < 1024; i++) { unsigned c = chunk[i]; chunk[i] = run; run += c; }
    }
    __syncthreads();
    unsigned c = chunk[tid];
    for (int k = 0; k < 64; k++) {
        unsigned bin = tid * 64 + k;
        unsigned h = 0;
#pragma unroll
        for (int r = 0; r < HREP; r++) h += g_hist1[r * 65536 + bin];
        if (RANK0 >= c && RANK0 < c + h) { g_bA = bin; g_cumA = c; }
        if (RANK1 >= c && RANK1 < c + h) { g_bB = bin; g_cumB = c; }
        c += h;
    }
}

__global__ void k_hist2() {
    unsigned bA = g_bA, bB = g_bB;
    const float* p = (const float*)g_Wc;
    int i = blockIdx.x * blockDim.x + threadIdx.x;
    int stride = gridDim.x * blockDim.x;
    for (; i < TOTAL; i += stride) {
        unsigned bits = __float_as_uint(p[i]);
        unsigned hi = bits >> 16;
        if (hi == bA) atomicAdd(&g_hist2a[bits & 0xFFFFu], 1u);
        if (hi == bB) atomicAdd(&g_hist2b[bits & 0xFFFFu], 1u);
    }
}

__device__ __forceinline__ void select_low(const unsigned* __restrict__ hist,
                                           unsigned rank, unsigned hi_bits,
                                           unsigned* chunk, float* out_val) {
    int tid = threadIdx.x;
    unsigned s = 0;
    for (int k = 0; k < 64; k++) s += hist[tid * 64 + k];
    chunk[tid] = s;
    __syncthreads();
    if (tid == 0) {
        unsigned run = 0;
        for (int i = 0; i < 1024; i++) { unsigned c = chunk[i]; chunk[i] = run; run += c; }
    }
    __syncthreads();
    unsigned c = chunk[tid];
    for (int k = 0; k < 64; k++) {
        unsigned h = hist[tid * 64 + k];
        if (rank >= c && rank < c + h)
            *out_val = __uint_as_float((hi_bits << 16) | (unsigned)(tid * 64 + k));
        c += h;
    }
    __syncthreads();
}

__global__ void k_sel2(const float* __restrict__ HtRM) {
    __shared__ unsigned chunk[1024];
    __shared__ float vsh[2];
    select_low(g_hist2a, RANK0 - g_cumA, g_bA, chunk, &vsh[0]);
    select_low(g_hist2b, RANK1 - g_cumB, g_bB, chunk, &vsh[1]);
    if (threadIdx.x == 0) {
        double pos = 0.99 * (double)(TOTAL - 1);
        double fr  = pos - floor(pos);
        double q = (double)vsh[0] + fr * ((double)vsh[1] - (double)vsh[0]);
        g_scale = HtRM[0] / (float)q;
    }
}

// ---------------------------------------------------------------------------
__global__ void k_final(const float* __restrict__ Wt, float* __restrict__ out) {
    __shared__ float sw[12];
    if (threadIdx.x < 12) sw[threadIdx.x] = Wt[threadIdx.x];
    __syncthreads();
    float wt[12];
#pragma unroll
    for (int t = 0; t < 12; t++) wt[t] = sw[t];
    float sc = g_scale;
    int i = blockIdx.x * blockDim.x + threadIdx.x;
    int stride = gridDim.x * blockDim.x;
    for (int p = i; p < N_PIX; p += stride) {
        float4 c4 = g_Wc[p];
        float h0 = c4.x * sc, h1 = c4.y * sc, h2 = c4.z * sc, h3 = c4.w * sc;
#pragma unroll
        for (int c = 0; c < 3; c++) {
            float t = wt[c*4+0]*h0 + wt[c*4+1]*h1 + wt[c*4+2]*h2 + wt[c*4+3]*h3;
            float o = __expf(-t);
            out[c * N_PIX + p] = fminf(fmaxf(o, 0.0f), 1.0f);
        }
    }
}

// ---------------------------------------------------------------------------
extern "C" void kernel_launch(void* const* d_in, const int* in_sizes, int n_in,
                              void* d_out, int out_size) {
    const float* pic = (const float*)d_in[0];
    const float* Wt  = (const float*)d_in[1];
    const float* Ht  = (const float*)d_in[2];
    const float* W0  = (const float*)d_in[3];
    const float* H0  = (const float*)d_in[4];
    float* out = (float*)d_out;

    // deterministic co-resident grid for the persistent kernel
    int sms = 148, nb = 0;
    cudaDeviceGetAttribute(&sms, cudaDevAttrMultiProcessorCount, 0);
    cudaOccupancyMaxActiveBlocksPerMultiprocessor(&nb, k_loop, NTHR, 0);
    if (nb < 1) nb = 1;
    if (nb > 2) nb = 2;
    int grid = sms * nb;
    if (grid > GRID_MAX) grid = GRID_MAX;

    k_init<<<4 * sms, 256>>>(pic, W0);
    k_loop<<<grid, NTHR>>>(H0);
    k_sel1<<<1, 1024>>>();
    k_hist2<<<4 * sms, 256>>>();
    k_sel2<<<1, 1024>>>(Ht);
    k_final<<<4 * sms, 256>>>(Wt, out);
}

// round 7
// speedup vs baseline: 1.4698x; 1.1485x over previous
#include <cuda_runtime.h>
#include <math.h>
#include <stdint.h>

// ---------------------------------------------------------------------------
// HE_ColorNormalization, register-resident persistent NMF.
//   d_in[0] pic float32 (3,1024,1024) | d_in[1] W_target (3,4) | d_in[2] Ht_RM ()
//   d_in[3] W0 (N,4) | d_in[4] H0 (3,4)    Output: float32 (3,1024,1024)
// Concentrations Wc live in REGISTERS for all 100 iterations (14 pixels/thread,
// grid 293 x 256, 2 CTAs/SM, 128-reg budget). Math uses packed fma.rn.f32x2.
// ---------------------------------------------------------------------------

#define N_PIX    1048576
#define N_ITERS  100
#define EPSF     1e-8f
#define CTATHR   256
#define PPT      14                      // pixels per thread
#define GRID_LOOP 293                    // ceil(N_PIX / (PPT*CTATHR))
#define TSTRIDE  (GRID_LOOP * CTATHR)    // 75008
#define TOTAL    (4 * N_PIX)
#define RANK0    4152359u                // floor(0.99*(TOTAL-1))
#define RANK1    4152360u
#define HREP     16

typedef unsigned long long u64;

__device__ __forceinline__ u64 pk2(float lo, float hi) {
    u64 r; asm("mov.b64 %0, {%1, %2};" : "=l"(r) : "f"(lo), "f"(hi)); return r;
}
__device__ __forceinline__ void upk2(u64 v, float& lo, float& hi) {
    asm("mov.b64 {%0, %1}, %2;" : "=f"(lo), "=f"(hi) : "l"(v));
}
__device__ __forceinline__ u64 fma2_(u64 a, u64 b, u64 c) {
    u64 d; asm("fma.rn.f32x2 %0, %1, %2, %3;" : "=l"(d) : "l"(a), "l"(b), "l"(c)); return d;
}
__device__ __forceinline__ u64 mul2_(u64 a, u64 b) {
    u64 d; asm("mul.rn.f32x2 %0, %1, %2;" : "=l"(d) : "l"(a), "l"(b)); return d;
}

// Scratch (static device globals: no allocation allowed)
__device__ float4   g_Vp[N_PIX];                 // packed OD (v0,v1,v2,unused)
__device__ float4   g_Wc[N_PIX];                 // concentrations (final only)
__device__ float    g_part[2][22][GRID_LOOP];
__device__ unsigned g_arrive;
__device__ unsigned g_hist1[HREP * 65536];
__device__ unsigned g_hist2a[65536];
__device__ unsigned g_hist2b[65536];
__device__ unsigned g_bA, g_bB, g_cumA, g_cumB;
__device__ float    g_scale;

__device__ __forceinline__ float od_clip(float x) {
    x = fminf(fmaxf(x, 0.01f), 0.99f);
    return -__logf(x);
}

// ---------------------------------------------------------------------------
__global__ void k_init(const float* __restrict__ pic,
                       const float* __restrict__ W0) {
    int i = blockIdx.x * blockDim.x + threadIdx.x;
    int stride = gridDim.x * blockDim.x;
    const float4* pic4 = (const float4*)pic;
    const float4* w04  = (const float4*)W0;
    const int NG = N_PIX / 4;
    for (int g = i; g < NG; g += stride) {
        float4 r = pic4[g];
        float4 gg = pic4[NG + g];
        float4 b = pic4[2 * NG + g];
        g_Vp[4*g+0] = make_float4(od_clip(r.x), od_clip(gg.x), od_clip(b.x), 0.f);
        g_Vp[4*g+1] = make_float4(od_clip(r.y), od_clip(gg.y), od_clip(b.y), 0.f);
        g_Vp[4*g+2] = make_float4(od_clip(r.z), od_clip(gg.z), od_clip(b.z), 0.f);
        g_Vp[4*g+3] = make_float4(od_clip(r.w), od_clip(gg.w), od_clip(b.w), 0.f);
    }
    for (int p = i; p < N_PIX; p += stride) g_Wc[p] = w04[p];
    uint4 z = make_uint4(0u, 0u, 0u, 0u);
    uint4* h1 = (uint4*)g_hist1;
    for (int h = i; h < HREP * 65536 / 4; h += stride) h1[h] = z;
    uint4* h2a = (uint4*)g_hist2a;
    uint4* h2b = (uint4*)g_hist2b;
    for (int h = i; h < 65536 / 4; h += stride) { h2a[h] = z; h2b[h] = z; }
    if (i == 0) g_arrive = 0u;
}

// ---------------------------------------------------------------------------
// Persistent loop. Wc in registers; one grid barrier per iteration; every CTA
// redundantly reduces the 22 partials in fixed order (deterministic).
// ---------------------------------------------------------------------------
__global__ __launch_bounds__(CTATHR, 2) void k_loop(const float* __restrict__ H0) {
    __shared__ float sHd[12];
    __shared__ float red[CTATHR / 32][22];
    __shared__ float tot[22];

    const int tid  = threadIdx.x;
    const int cta  = blockIdx.x;
    const int warp = tid >> 5, lane = tid & 31;
    const int base = cta * CTATHR + tid;

    if (tid < 12) sHd[tid] = H0[tid];

    // Wc prologue load -> registers for the whole run
    float4 wreg[PPT];
#pragma unroll
    for (int k = 0; k < PPT; k++) {
        int p = base + k * TSTRIDE;
        if (k < PPT - 1 || p < N_PIX) wreg[k] = g_Wc[p];
        else                          wreg[k] = make_float4(0.f, 0.f, 0.f, 0.f);
    }
    __syncthreads();

    unsigned* hist = &g_hist1[(cta & (HREP - 1)) * 65536];

    for (int iter = 0; iter < N_ITERS; iter++) {
        float hd[12];
#pragma unroll
        for (int t = 0; t < 12; t++) hd[t] = sHd[t];

        float G[16];
#pragma unroll
        for (int k = 0; k < 4; k++)
#pragma unroll
            for (int j = 0; j < 4; j++)
                G[k*4+j] = hd[k]*hd[j] + hd[4+k]*hd[4+j] + hd[8+k]*hd[8+j];

        u64 hd2[3][2], G2[4][2];
#pragma unroll
        for (int c = 0; c < 3; c++) {
            hd2[c][0] = pk2(hd[c*4+0], hd[c*4+1]);
            hd2[c][1] = pk2(hd[c*4+2], hd[c*4+3]);
        }
#pragma unroll
        for (int k = 0; k < 4; k++) {
            G2[k][0] = pk2(G[k*4+0], G[k*4+1]);
            G2[k][1] = pk2(G[k*4+2], G[k*4+3]);
        }
        const u64 eps2 = pk2(EPSF, EPSF);

        u64 aA[3][2], aB[4][2];
#pragma unroll
        for (int c = 0; c < 3; c++) { aA[c][0] = 0ull; aA[c][1] = 0ull; }
#pragma unroll
        for (int j = 0; j < 4; j++) { aB[j][0] = 0ull; aB[j][1] = 0ull; }

        const bool last = (iter == N_ITERS - 1);

#pragma unroll
        for (int k = 0; k < PPT; k++) {
            int p = base + k * TSTRIDE;
            if (k == PPT - 1 && p >= N_PIX) continue;
            float4 v = g_Vp[p];
            float4 w = wreg[k];

            u64 vb0 = pk2(v.x, v.x), vb1 = pk2(v.y, v.y), vb2 = pk2(v.z, v.z);
            u64 n0 = fma2_(vb0, hd2[0][0], fma2_(vb1, hd2[1][0], mul2_(vb2, hd2[2][0])));
            u64 n1 = fma2_(vb0, hd2[0][1], fma2_(vb1, hd2[1][1], mul2_(vb2, hd2[2][1])));

            u64 wb0 = pk2(w.x, w.x), wb1 = pk2(w.y, w.y);
            u64 wb2 = pk2(w.z, w.z), wb3 = pk2(w.w, w.w);
            u64 d0 = fma2_(wb0, G2[0][0], fma2_(wb1, G2[1][0],
                     fma2_(wb2, G2[2][0], fma2_(wb3, G2[3][0], eps2))));
            u64 d1 = fma2_(wb0, G2[0][1], fma2_(wb1, G2[1][1],
                     fma2_(wb2, G2[2][1], fma2_(wb3, G2[3][1], eps2))));

            float num0, num1, num2, num3, den0, den1, den2, den3;
            upk2(n0, num0, num1); upk2(n1, num2, num3);
            upk2(d0, den0, den1); upk2(d1, den2, den3);

            float nw0 = w.x * __fdividef(num0, den0);
            float nw1 = w.y * __fdividef(num1, den1);
            float nw2 = w.z * __fdividef(num2, den2);
            float nw3 = w.w * __fdividef(num3, den3);
            wreg[k] = make_float4(nw0, nw1, nw2, nw3);

            u64 nwp0 = pk2(nw0, nw1), nwp1 = pk2(nw2, nw3);
            aA[0][0] = fma2_(vb0, nwp0, aA[0][0]); aA[0][1] = fma2_(vb0, nwp1, aA[0][1]);
            aA[1][0] = fma2_(vb1, nwp0, aA[1][0]); aA[1][1] = fma2_(vb1, nwp1, aA[1][1]);
            aA[2][0] = fma2_(vb2, nwp0, aA[2][0]); aA[2][1] = fma2_(vb2, nwp1, aA[2][1]);

            u64 nb0 = pk2(nw0, nw0), nb1 = pk2(nw1, nw1);
            u64 nb2 = pk2(nw2, nw2), nb3 = pk2(nw3, nw3);
            aB[0][0] = fma2_(nb0, nwp0, aB[0][0]); aB[0][1] = fma2_(nb0, nwp1, aB[0][1]);
            aB[1][0] = fma2_(nb1, nwp0, aB[1][0]); aB[1][1] = fma2_(nb1, nwp1, aB[1][1]);
            aB[2][0] = fma2_(nb2, nwp0, aB[2][0]); aB[2][1] = fma2_(nb2, nwp1, aB[2][1]);
            aB[3][0] = fma2_(nb3, nwp0, aB[3][0]); aB[3][1] = fma2_(nb3, nwp1, aB[3][1]);

            if (last) {
                g_Wc[p] = wreg[k];
                atomicAdd(&hist[__float_as_uint(nw0) >> 16], 1u);
                atomicAdd(&hist[__float_as_uint(nw1) >> 16], 1u);
                atomicAdd(&hist[__float_as_uint(nw2) >> 16], 1u);
                atomicAdd(&hist[__float_as_uint(nw3) >> 16], 1u);
            }
        }

        if (last) break;   // stores/atomics flushed at kernel completion

        float acc[22];
        upk2(aA[0][0], acc[0],  acc[1]);  upk2(aA[0][1], acc[2],  acc[3]);
        upk2(aA[1][0], acc[4],  acc[5]);  upk2(aA[1][1], acc[6],  acc[7]);
        upk2(aA[2][0], acc[8],  acc[9]);  upk2(aA[2][1], acc[10], acc[11]);
        {
            float B00,B01,B02,B03,B10,B11,B12,B13,B20,B21,B22,B23,B30,B31,B32,B33;
            upk2(aB[0][0],B00,B01); upk2(aB[0][1],B02,B03);
            upk2(aB[1][0],B10,B11); upk2(aB[1][1],B12,B13);
            upk2(aB[2][0],B20,B21); upk2(aB[2][1],B22,B23);
            upk2(aB[3][0],B30,B31); upk2(aB[3][1],B32,B33);
            acc[12]=B00; acc[13]=B01; acc[14]=B02; acc[15]=B03;
            acc[16]=B11; acc[17]=B12; acc[18]=B13;
            acc[19]=B22; acc[20]=B23; acc[21]=B33;
            (void)B10; (void)B20; (void)B21; (void)B30; (void)B31; (void)B32;
        }

        // CTA reduction
#pragma unroll
        for (int t = 0; t < 22; t++)
#pragma unroll
            for (int off = 16; off > 0; off >>= 1)
                acc[t] += __shfl_down_sync(0xFFFFFFFFu, acc[t], off);
        if (lane == 0) {
#pragma unroll
            for (int t = 0; t < 22; t++) red[warp][t] = acc[t];
        }
        __syncthreads();
        if (tid < 22) {
            float s = 0.0f;
#pragma unroll
            for (int w = 0; w < CTATHR / 32; w++) s += red[w][tid];
            g_part[iter & 1][tid][cta] = s;
        }
        __syncthreads();

        // grid barrier (generation counter; reset each replay by k_init)
        if (tid == 0) {
            __threadfence();
            atomicAdd(&g_arrive, 1u);
            const unsigned target = (unsigned)(iter + 1) * (unsigned)GRID_LOOP;
            const volatile unsigned* va = &g_arrive;
            while (*va < target) __nanosleep(32);
            __threadfence();
        }
        __syncthreads();

        // every CTA reduces all partials in fixed order (deterministic)
        for (int v = warp; v < 22; v += CTATHR / 32) {
            float s = 0.0f;
            for (int b = lane; b < GRID_LOOP; b += 32) s += g_part[iter & 1][v][b];
#pragma unroll
            for (int off = 16; off > 0; off >>= 1)
                s += __shfl_down_sync(0xFFFFFFFFu, s, off);
            if (lane == 0) tot[v] = s;
        }
        __syncthreads();

        if (tid == 0) {
            const int map[16] = {0,1,2,3, 1,4,5,6, 2,5,7,8, 3,6,8,9};
            float B[16];
#pragma unroll
            for (int t = 0; t < 16; t++) B[t] = tot[12 + map[t]];
#pragma unroll
            for (int c = 0; c < 3; c++)
#pragma unroll
                for (int j = 0; j < 4; j++) {
                    float den = hd[c*4+0]*B[0*4+j] + hd[c*4+1]*B[1*4+j]
                              + hd[c*4+2]*B[2*4+j] + hd[c*4+3]*B[3*4+j] + EPSF;
                    sHd[c*4+j] = hd[c*4+j] * tot[c*4+j] / den;
                }
        }
        __syncthreads();
    }
}

// ---------------------------------------------------------------------------
__global__ void k_sel1() {
    __shared__ unsigned chunk[1024];
    int tid = threadIdx.x;
    unsigned s = 0;
    for (int k = 0; k < 64; k++) {
        unsigned bin = tid * 64 + k;
        unsigned c = 0;
#pragma unroll
        for (int r = 0; r < HREP; r++) c += g_hist1[r * 65536 + bin];
        s += c;
    }
    chunk[tid] = s;
    __syncthreads();
    if (tid == 0) {
        unsigned run = 0;
        for (int i = 0; i < 1024; i++) { unsigned c = chunk[i]; chunk[i] = run; run += c; }
    }
    __syncthreads();
    unsigned c = chunk[tid];
    for (int k = 0; k < 64; k++) {
        unsigned bin = tid * 64 + k;
        unsigned h = 0;
#pragma unroll
        for (int r = 0; r < HREP; r++) h += g_hist1[r * 65536 + bin];
        if (RANK0 >= c && RANK0 < c + h) { g_bA = bin; g_cumA = c; }
        if (RANK1 >= c && RANK1 < c + h) { g_bB = bin; g_cumB = c; }
        c += h;
    }
}

__global__ void k_hist2() {
    unsigned bA = g_bA, bB = g_bB;
    const uint4* p = (const uint4*)g_Wc;
    int i = blockIdx.x * blockDim.x + threadIdx.x;
    int stride = gridDim.x * blockDim.x;
    for (; i < N_PIX; i += stride) {
        uint4 u = p[i];
        unsigned h0 = u.x >> 16, h1 = u.y >> 16, h2 = u.z >> 16, h3 = u.w >> 16;
        if (h0 == bA) atomicAdd(&g_hist2a[u.x & 0xFFFFu], 1u);
        if (h0 == bB) atomicAdd(&g_hist2b[u.x & 0xFFFFu], 1u);
        if (h1 == bA) atomicAdd(&g_hist2a[u.y & 0xFFFFu], 1u);
        if (h1 == bB) atomicAdd(&g_hist2b[u.y & 0xFFFFu], 1u);
        if (h2 == bA) atomicAdd(&g_hist2a[u.z & 0xFFFFu], 1u);
        if (h2 == bB) atomicAdd(&g_hist2b[u.z & 0xFFFFu], 1u);
        if (h3 == bA) atomicAdd(&g_hist2a[u.w & 0xFFFFu], 1u);
        if (h3 == bB) atomicAdd(&g_hist2b[u.w & 0xFFFFu], 1u);
    }
}

__device__ __forceinline__ void select_low(const unsigned* __restrict__ hist,
                                           unsigned rank, unsigned hi_bits,
                                           unsigned* chunk, float* out_val) {
    int tid = threadIdx.x;
    unsigned s = 0;
    for (int k = 0; k < 64; k++) s += hist[tid * 64 + k];
    chunk[tid] = s;
    __syncthreads();
    if (tid == 0) {
        unsigned run = 0;
        for (int i = 0; i < 1024; i++) { unsigned c = chunk[i]; chunk[i] = run; run += c; }
    }
    __syncthreads();
    unsigned c = chunk[tid];
    for (int k = 0; k < 64; k++) {
        unsigned h = hist[tid * 64 + k];
        if (rank >= c && rank < c + h)
            *out_val = __uint_as_float((hi_bits << 16) | (unsigned)(tid * 64 + k));
        c += h;
    }
    __syncthreads();
}

__global__ void k_sel2(const float* __restrict__ HtRM) {
    __shared__ unsigned chunk[1024];
    __shared__ float vsh[2];
    select_low(g_hist2a, RANK0 - g_cumA, g_bA, chunk, &vsh[0]);
    select_low(g_hist2b, RANK1 - g_cumB, g_bB, chunk, &vsh[1]);
    if (threadIdx.x == 0) {
        double pos = 0.99 * (double)(TOTAL - 1);
        double fr  = pos - floor(pos);
        double q = (double)vsh[0] + fr * ((double)vsh[1] - (double)vsh[0]);
        g_scale = HtRM[0] / (float)q;
    }
}

// ---------------------------------------------------------------------------
__global__ void k_final(const float* __restrict__ Wt, float* __restrict__ out) {
    __shared__ float sw[12];
    if (threadIdx.x < 12) sw[threadIdx.x] = Wt[threadIdx.x];
    __syncthreads();
    float wt[12];
#pragma unroll
    for (int t = 0; t < 12; t++) wt[t] = sw[t];
    float sc = g_scale;
    const int NG = N_PIX / 4;
    float4* out4 = (float4*)out;
    int i = blockIdx.x * blockDim.x + threadIdx.x;
    int stride = gridDim.x * blockDim.x;
    for (int g = i; g < NG; g += stride) {
        float4 cc[4];
#pragma unroll
        for (int q = 0; q < 4; q++) {
            float4 c4 = g_Wc[4 * g + q];
            cc[q] = make_float4(c4.x * sc, c4.y * sc, c4.z * sc, c4.w * sc);
        }
#pragma unroll
        for (int c = 0; c < 3; c++) {
            float4 o;
            float* op = &o.x;
#pragma unroll
            for (int q = 0; q < 4; q++) {
                float t = wt[c*4+0]*cc[q].x + wt[c*4+1]*cc[q].y
                        + wt[c*4+2]*cc[q].z + wt[c*4+3]*cc[q].w;
                float e = __expf(-t);
                op[q] = fminf(fmaxf(e, 0.0f), 1.0f);
            }
            out4[c * NG + g] = o;
        }
    }
}

// ---------------------------------------------------------------------------
extern "C" void kernel_launch(void* const* d_in, const int* in_sizes, int n_in,
                              void* d_out, int out_size) {
    const float* pic = (const float*)d_in[0];
    const float* Wt  = (const float*)d_in[1];
    const float* Ht  = (const float*)d_in[2];
    const float* W0  = (const float*)d_in[3];
    const float* H0  = (const float*)d_in[4];
    float* out = (float*)d_out;

    k_init<<<592, 256>>>(pic, W0);
    k_loop<<<GRID_LOOP, CTATHR>>>(H0);    // 293 CTAs, 2/SM guaranteed co-resident
    k_sel1<<<1, 1024>>>();
    k_hist2<<<592, 256>>>();
    k_sel2<<<1, 1024>>>(Ht);
    k_final<<<592, 256>>>(Wt, out);
}